// round 15
// baseline (speedup 1.0000x reference)
#include <cuda_runtime.h>
#include <math.h>

#define IN_N   4096
#define H_S    250
#define H_R    100
#define V      40
#define TMAX   30
#define OUT_N  262144
#define NB_S   50       // sender blocks
#define NB_R   10       // receiver blocks
#define NB     60
#define SLS    5        // sender h rows per block (50*5 = 250)
#define SLR    10       // receiver h rows per block (10*10 = 100)
#define NT     256
#define PADS   256
#define PADR   128

// ---- global scratch (no allocations; zero-initialized at load) ----
__device__ __align__(16) float g_nh[2][PADS];   // sender hidden, parity buffered (pads stay 0)
__device__ __align__(16) float g_hr[2][PADR];   // receiver hidden, parity buffered
__device__ __align__(16) float g_lp[2][V][64];  // partial logits; slots 50..63 stay 0 forever
__device__ __align__(16) float g_hr_final[H_R];
struct Flag128 { unsigned v; unsigned pad[31]; };
__device__ Flag128  g_flags[NB];                // reset by k_scale for next replay
__device__ unsigned g_done;                     // k_logits last-block counter (self-resetting)
__device__ float    g_partials[1024];
__device__ float    g_inv;

// ---- smem layout (floats) ----
#define O_WHH   0       // 5120  (S: 20x256, R: 40x128 — both 5120)
#define O_WIH   5120    // 1600  (S: 20x40, R: 40x40)
#define O_BIAS  6720    // 40
#define O_GATES 6760    // 40
#define O_C     6800    // 12
#define O_WP    6812    // 40 x 5 = 200
#define O_BP    7012    // 44
#define O_CTRL  7056    // 4
#define O_GUM   7060    // 1200
#define SMEM_FLOATS 8260
#define SMEM_BYTES  (SMEM_FLOATS * 4)

__device__ __forceinline__ float fsig(float v)  { return __fdividef(1.0f, 1.0f + __expf(-v)); }
__device__ __forceinline__ float ftanh(float v) { return 1.0f - __fdividef(2.0f, __expf(2.0f * v) + 1.0f); }

// Contention-free grid barrier: arrivals and polls hit DISTINCT L2 lines.
__device__ __forceinline__ void grid_barrier(unsigned step, int tid, int blk) {
    __syncthreads();
    if (tid == 0)
        asm volatile("st.release.gpu.global.u32 [%0], %1;"
                     :: "l"(&g_flags[blk].v), "r"(step) : "memory");
    if (tid < NB) {
        unsigned v;
        do {
            asm volatile("ld.acquire.gpu.u32 %0, [%1];"
                         : "=r"(v) : "l"(&g_flags[tid].v) : "memory");
        } while (v < step);
    }
    __syncthreads();
}

extern __shared__ float sm[];

__global__ void __launch_bounds__(NT) net_kernel(
    const float* __restrict__ x,    const float* __restrict__ gum,
    const float* __restrict__ Ws1,  const float* __restrict__ bs1,
    const float* __restrict__ Wih1, const float* __restrict__ Whh1,
    const float* __restrict__ bih1, const float* __restrict__ bhh1,
    const float* __restrict__ Wp,   const float* __restrict__ bp,
    const float* __restrict__ Wih2, const float* __restrict__ Whh2,
    const float* __restrict__ bih2, const float* __restrict__ bhh2)
{
    const int tid  = threadIdx.x;
    const int warp = tid >> 5;
    const int lane = tid & 31;
    const int blk  = blockIdx.x;
    const bool isS = (blk < NB_S);
    const int rb   = blk - NB_S;

    float* s_whh  = sm + O_WHH;
    float* s_wih  = sm + O_WIH;
    float* s_bias = sm + O_BIAS;
    float* s_gates= sm + O_GATES;
    float* s_c    = sm + O_C;
    float* s_wp   = sm + O_WP;
    float* s_bp   = sm + O_BP;
    int*   s_ctrl = (int*)(sm + O_CTRL);
    float* s_gum  = sm + O_GUM;

    // ---------------- prologue ----------------
    if (tid < V) s_bp[tid] = bp[tid];
    for (int i = tid; i < TMAX * V; i += NT) s_gum[i] = gum[i];

    if (isS) {
        for (int i = tid; i < 4 * SLS * PADS; i += NT) {
            int r = i >> 8, k = i & (PADS - 1);
            int g = r / SLS, j = r - g * SLS;
            int R = g * H_S + blk * SLS + j;
            s_whh[i] = (k < H_S) ? Whh1[R * H_S + k] : 0.0f;
        }
        for (int i = tid; i < 4 * SLS * V; i += NT) {
            int r = i / V, k = i - r * V;
            int g = r / SLS, j = r - g * SLS;
            int R = g * H_S + blk * SLS + j;
            s_wih[i] = Wih1[R * V + k];
        }
        if (tid < 4 * SLS) {
            int g = tid / SLS, j = tid - g * SLS;
            int R = g * H_S + blk * SLS + j;
            s_bias[tid] = bih1[R] + bhh1[R];
        }
        if (tid < SLS) s_c[tid] = 0.0f;
        for (int i = tid; i < V * SLS; i += NT) {
            int r = i / SLS, j = i - r * SLS;
            s_wp[i] = Wp[r * H_S + blk * SLS + j];
        }
        // h0 rows (warps 0..4, one row each)
        if (warp < SLS) {
            int row = blk * SLS + warp;
            const float4* wr = (const float4*)(Ws1 + (size_t)row * IN_N);
            const float4* xv = (const float4*)x;
            float acc = 0.0f;
            for (int i = lane; i < IN_N / 4; i += 32) {
                float4 w = wr[i], xx = xv[i];
                acc += w.x * xx.x + w.y * xx.y + w.z * xx.z + w.w * xx.w;
            }
#pragma unroll
            for (int o = 16; o; o >>= 1) acc += __shfl_xor_sync(0xffffffffu, acc, o);
            if (lane == 0) {
                float v = acc + bs1[row];
                g_nh[0][row] = v > 0.0f ? v : 0.0f;
            }
        }
    } else {
        for (int i = tid; i < 4 * SLR * PADR; i += NT) {
            int r = i >> 7, k = i & (PADR - 1);
            int g = r / SLR, j = r - g * SLR;
            int R = g * H_R + rb * SLR + j;
            s_whh[i] = (k < H_R) ? Whh2[R * H_R + k] : 0.0f;
        }
        for (int i = tid; i < 4 * SLR * V; i += NT) {
            int r = i / V, k = i - r * V;
            int g = r / SLR, j = r - g * SLR;
            int R = g * H_R + rb * SLR + j;
            s_wih[i] = Wih2[R * V + k];
        }
        if (tid < 4 * SLR) {
            int g = tid / SLR, j = tid - g * SLR;
            int R = g * H_R + rb * SLR + j;
            s_bias[tid] = bih2[R] + bhh2[R];
        }
        if (tid < SLR) s_c[tid] = 0.0f;
        // re-zero hr exchange buffers for this replay (single block)
        if (rb == 0 && tid < PADR) { g_hr[0][tid] = 0.0f; g_hr[1][tid] = 0.0f; }
    }

    unsigned step = 1;
    grid_barrier(step, tid, blk); step++;

    // ---------------- segments ----------------
    // S(t): warp0 resolves sym(t-1) (t>=2) WHILE warps 1..5 run the matvecs.
    // After join: column add + pointwise (+ fused lp in warp 1). One barrier per segment.
    for (int t = 1; t <= TMAX + 1; t++) {
        const int pp = (t - 1) & 1;     // parity of nh(t-1) / lp(t-1)

        if (warp == 0) {
            if (t >= 2) {
                if (t - 1 == TMAX) {
                    if (lane == 0) s_ctrl[0] = V - 1;    // forced EOS at max length
                } else {
                    // logits(t-1) = bp + gum[t-2] + sum_b lp(t-1)[v][b]  (64 slots, 50..63 = 0)
                    const float4* p4 = (const float4*)&g_lp[pp][lane][0];
                    float bv = s_bp[lane] + s_gum[(t - 2) * V + lane];
#pragma unroll
                    for (int m = 0; m < 16; m++) {
                        float4 a = __ldcg(p4 + m);
                        bv += (a.x + a.y) + (a.z + a.w);
                    }
                    int bi = lane;
                    if (lane < V - 32) {
                        int v2 = 32 + lane;
                        const float4* q4 = (const float4*)&g_lp[pp][v2][0];
                        float l2 = s_bp[v2] + s_gum[(t - 2) * V + v2];
#pragma unroll
                        for (int m = 0; m < 16; m++) {
                            float4 a = __ldcg(q4 + m);
                            l2 += (a.x + a.y) + (a.z + a.w);
                        }
                        if (l2 > bv) { bv = l2; bi = v2; }   // strict: ties keep lower idx
                    }
#pragma unroll
                    for (int o = 16; o; o >>= 1) {
                        float ov = __shfl_xor_sync(0xffffffffu, bv, o);
                        int   oi = __shfl_xor_sync(0xffffffffu, bi, o);
                        if (ov > bv || (ov == bv && oi < bi)) { bv = ov; bi = oi; }
                    }
                    if (lane == 0) s_ctrl[0] = bi;
                }
            }
        } else if (isS && warp <= 5) {
            // sender matvec: 20 gate rows, 4 per warp (warps 1..5)
            float4 h0v = __ldcg((const float4*)g_nh[pp] + lane);
            float4 h1v = __ldcg((const float4*)g_nh[pp] + 32 + lane);
            float acc[4];
#pragma unroll
            for (int u = 0; u < 4; u++) {
                const float4* wr = (const float4*)(s_whh + ((warp - 1) * 4 + u) * PADS);
                float4 w0 = wr[lane], w1 = wr[lane + 32];
                acc[u] = w0.x * h0v.x + w0.y * h0v.y + w0.z * h0v.z + w0.w * h0v.w
                       + w1.x * h1v.x + w1.y * h1v.y + w1.z * h1v.z + w1.w * h1v.w;
            }
#pragma unroll
            for (int o = 16; o; o >>= 1) {
#pragma unroll
                for (int u = 0; u < 4; u++) acc[u] += __shfl_xor_sync(0xffffffffu, acc[u], o);
            }
            if (lane == 0) {
#pragma unroll
                for (int u = 0; u < 4; u++) {
                    int r = (warp - 1) * 4 + u;
                    s_gates[r] = acc[u] + s_bias[r];
                }
            }
        } else if (!isS && t >= 2 && warp <= 5) {
            // receiver matvec: 40 gate rows, 8 per warp (warps 1..5)
            float4 hv = __ldcg((const float4*)g_hr[t & 1] + lane);   // hr(t-2)
            float acc[8];
#pragma unroll
            for (int u = 0; u < 8; u++) {
                float4 w = ((const float4*)(s_whh + ((warp - 1) * 8 + u) * PADR))[lane];
                acc[u] = w.x * hv.x + w.y * hv.y + w.z * hv.z + w.w * hv.w;
            }
#pragma unroll
            for (int o = 16; o; o >>= 1) {
#pragma unroll
                for (int u = 0; u < 8; u++) acc[u] += __shfl_xor_sync(0xffffffffu, acc[u], o);
            }
            if (lane == 0) {
#pragma unroll
                for (int u = 0; u < 8; u++) {
                    int r = (warp - 1) * 8 + u;
                    s_gates[r] = acc[u] + s_bias[r];
                }
            }
        }
        __syncthreads();   // join: gates ready AND sym resolved

        const int sym = (t >= 2) ? s_ctrl[0] : -1;
        const bool last = (sym == V - 1);

        if (!isS && t >= 2 && tid < SLR) {       // receiver pointwise: hr(t-1)
            float gi = s_gates[tid]           + s_wih[(tid)           * V + sym];
            float gf = s_gates[SLR + tid]     + s_wih[(SLR + tid)     * V + sym];
            float gg = s_gates[2 * SLR + tid] + s_wih[(2 * SLR + tid) * V + sym];
            float go = s_gates[3 * SLR + tid] + s_wih[(3 * SLR + tid) * V + sym];
            float cn = fsig(gf) * s_c[tid] + fsig(gi) * ftanh(gg);
            s_c[tid] = cn;
            float hr = fsig(go) * ftanh(cn);
            if (last) g_hr_final[rb * SLR + tid] = hr;
            else      g_hr[(t - 1) & 1][rb * SLR + tid] = hr;
        }
        if (last) break;

        if (isS && warp == 1) {
            // sender pointwise (lanes 0..4) + fused lp via shfl broadcast (all lanes)
            float nhv = 0.0f;
            if (lane < SLS) {
                float gi = s_gates[lane],           gf = s_gates[SLS + lane];
                float gg = s_gates[2 * SLS + lane], go = s_gates[3 * SLS + lane];
                if (sym >= 0) {
                    gi += s_wih[(lane)           * V + sym];
                    gf += s_wih[(SLS + lane)     * V + sym];
                    gg += s_wih[(2 * SLS + lane) * V + sym];
                    go += s_wih[(3 * SLS + lane) * V + sym];
                }
                float cn = fsig(gf) * s_c[lane] + fsig(gi) * ftanh(gg);
                s_c[lane] = cn;
                nhv = fsig(go) * ftanh(cn);
                g_nh[t & 1][blk * SLS + lane] = nhv;
            }
            float h0 = __shfl_sync(0xffffffffu, nhv, 0);
            float h1 = __shfl_sync(0xffffffffu, nhv, 1);
            float h2 = __shfl_sync(0xffffffffu, nhv, 2);
            float h3 = __shfl_sync(0xffffffffu, nhv, 3);
            float h4 = __shfl_sync(0xffffffffu, nhv, 4);
            {
                const float* wv = s_wp + lane * SLS;
                float a = wv[0] * h0 + wv[1] * h1 + wv[2] * h2 + wv[3] * h3 + wv[4] * h4;
                g_lp[t & 1][lane][blk] = a;
            }
            if (lane < V - 32) {
                int v2 = 32 + lane;
                const float* wv = s_wp + v2 * SLS;
                float a = wv[0] * h0 + wv[1] * h1 + wv[2] * h2 + wv[3] * h3 + wv[4] * h4;
                g_lp[t & 1][v2][blk] = a;
            }
        }

        grid_barrier(step, tid, blk); step++;
    }
}

// ---------------- final stage: softmax(W_r @ hR + b_r) ----------------
// Register-rotation version (measured tail 24.2us vs 35.7us for the smem tile).
// logits tiny (weights *0.05, |h|<1): exp can't overflow, no max subtraction.

__global__ void __launch_bounds__(256) k_logits(const float* __restrict__ Wr,
                                                const float* __restrict__ br,
                                                float* __restrict__ out)
{
    __shared__ float sh[PADR];
    __shared__ float wsum[8];
    __shared__ float red[256];
    __shared__ int isLast;
    int tid = threadIdx.x, warp = tid >> 5, lane = tid & 31;
    if (tid < H_R) sh[tid] = g_hr_final[tid];
    else if (tid < PADR) sh[tid] = 0.0f;
    __syncthreads();

    float4 hv = make_float4(0.f, 0.f, 0.f, 0.f);
    if (lane < H_R / 4) hv = ((const float4*)sh)[lane];

    int base = (blockIdx.x * 8 + warp) * 32;
    float myacc = 0.0f;
#pragma unroll
    for (int b = 0; b < 8; b++) {
        float acc[4];
#pragma unroll
        for (int j = 0; j < 4; j++) {
            int row = base + b * 4 + j;
            float4 w = make_float4(0.f, 0.f, 0.f, 0.f);
            if (lane < H_R / 4)
                w = __ldg((const float4*)(Wr + (size_t)row * H_R) + lane);
            acc[j] = w.x * hv.x + w.y * hv.y + w.z * hv.z + w.w * hv.w;
        }
#pragma unroll
        for (int o = 16; o; o >>= 1) {
#pragma unroll
            for (int j = 0; j < 4; j++) acc[j] += __shfl_xor_sync(0xffffffffu, acc[j], o);
        }
#pragma unroll
        for (int j = 0; j < 4; j++)
            if (lane == b * 4 + j) myacc = acc[j];   // rotate: lane i keeps row base+i
    }
    float e = __expf(myacc + br[base + lane]);
    out[base + lane] = e;                            // fully coalesced store
    float es = e;
#pragma unroll
    for (int o = 16; o; o >>= 1) es += __shfl_xor_sync(0xffffffffu, es, o);
    if (lane == 0) wsum[warp] = es;
    __syncthreads();
    if (tid == 0) {
        float s2 = 0.0f;
#pragma unroll
        for (int w = 0; w < 8; w++) s2 += wsum[w];
        g_partials[blockIdx.x] = s2;                 // fixed order: deterministic
        unsigned old;
        asm volatile("atom.acq_rel.gpu.global.add.u32 %0, [%1], 1;"
                     : "=r"(old) : "l"(&g_done) : "memory");
        isLast = (old == 1023u);
    }
    __syncthreads();
    if (isLast) {
        float s = g_partials[tid] + g_partials[tid + 256]
                + g_partials[tid + 512] + g_partials[tid + 768];  // fixed order
        red[tid] = s;
        __syncthreads();
#pragma unroll
        for (int o = 128; o; o >>= 1) {
            if (tid < o) red[tid] += red[tid + o];
            __syncthreads();
        }
        if (tid == 0) {
            g_inv = 1.0f / red[0];
            g_done = 0u;                             // self-reset for next replay
        }
    }
}

__global__ void __launch_bounds__(256) k_scale(float* __restrict__ out)
{
    int i = blockIdx.x * 256 + threadIdx.x;
    out[i] *= g_inv;
    if (blockIdx.x == 0 && threadIdx.x < NB) g_flags[threadIdx.x].v = 0u;  // reset barrier
}

extern "C" void kernel_launch(void* const* d_in, const int* in_sizes, int n_in,
                              void* d_out, int out_size)
{
    (void)in_sizes; (void)n_in; (void)out_size;
    const float* x    = (const float*)d_in[0];
    const float* gum  = (const float*)d_in[1];
    const float* Ws1  = (const float*)d_in[2];
    const float* bs1  = (const float*)d_in[3];
    const float* Wih1 = (const float*)d_in[4];
    const float* Whh1 = (const float*)d_in[5];
    const float* bih1 = (const float*)d_in[6];
    const float* bhh1 = (const float*)d_in[7];
    const float* Wp   = (const float*)d_in[8];
    const float* bp   = (const float*)d_in[9];
    const float* Wih2 = (const float*)d_in[10];
    const float* Whh2 = (const float*)d_in[11];
    const float* bih2 = (const float*)d_in[12];
    const float* bhh2 = (const float*)d_in[13];
    const float* Wr   = (const float*)d_in[14];
    const float* br   = (const float*)d_in[15];
    float* out = (float*)d_out;

    cudaFuncSetAttribute(net_kernel, cudaFuncAttributeMaxDynamicSharedMemorySize, SMEM_BYTES);

    net_kernel<<<NB, NT, SMEM_BYTES>>>(x, gum, Ws1, bs1, Wih1, Whh1, bih1, bhh1,
                                       Wp, bp, Wih2, Whh2, bih2, bhh2);
    k_logits<<<1024, 256>>>(Wr, br, out);
    k_scale<<<OUT_N / 256, 256>>>(out);
}

// round 16
// speedup vs baseline: 1.2243x; 1.2243x over previous
#include <cuda_runtime.h>
#include <math.h>

#define IN_N   4096
#define H_S    250
#define H_R    100
#define V      40
#define TMAX   30
#define OUT_N  262144
#define NB_S   25
#define NB_R   5
#define NB     30
#define SLS    10       // sender h rows per block
#define SLR    20       // receiver h rows per block
#define NT     256
#define PADS   256
#define PADR   128

// ---- global scratch (no allocations; zero-initialized at load) ----
__device__ __align__(16) float g_nh[2][PADS];   // sender hidden, parity buffered (pads stay 0)
__device__ __align__(16) float g_hr[2][PADR];   // receiver hidden, parity buffered
__device__ __align__(16) float g_lp[2][V][32];  // partial logits; slots 25..31 stay 0 forever
__device__ __align__(16) float g_hr_final[H_R];
struct Flag128 { unsigned v; unsigned pad[31]; };
__device__ Flag128  g_flags[NB];                // reset by k_scale for next replay
__device__ unsigned g_done;                     // k_logits last-block counter (self-resetting)
__device__ float    g_partials[1024];
__device__ float    g_inv;

// ---- smem layout (floats) ----
#define O_WHH   0       // 10240  (S: 40x256, R: 80x128 — both 10240)
#define O_WIH   10240   // 3200   (S: 40x40, R: 80x40)
#define O_BIAS  13440   // 80
#define O_GATES 13520   // 80
#define O_C     13600   // 20
#define O_NH    13620   // 12
#define O_WP    13632   // 400
#define O_BP    14032   // 40
#define O_CTRL  14072   // 4
#define O_GUM   14080   // 1200
#define SMEM_FLOATS 15280
#define SMEM_BYTES  (SMEM_FLOATS * 4)

__device__ __forceinline__ float fsig(float v)  { return __fdividef(1.0f, 1.0f + __expf(-v)); }
__device__ __forceinline__ float ftanh(float v) { return 1.0f - __fdividef(2.0f, __expf(2.0f * v) + 1.0f); }

// Contention-free grid barrier: arrivals and polls hit DISTINCT L2 lines.
__device__ __forceinline__ void grid_barrier(unsigned step, int tid, int blk) {
    __syncthreads();
    if (tid == 0)
        asm volatile("st.release.gpu.global.u32 [%0], %1;"
                     :: "l"(&g_flags[blk].v), "r"(step) : "memory");
    if (tid < NB) {
        unsigned v;
        do {
            asm volatile("ld.acquire.gpu.u32 %0, [%1];"
                         : "=r"(v) : "l"(&g_flags[tid].v) : "memory");
        } while (v < step);
    }
    __syncthreads();
}

extern __shared__ float sm[];

__global__ void __launch_bounds__(NT) net_kernel(
    const float* __restrict__ x,    const float* __restrict__ gum,
    const float* __restrict__ Ws1,  const float* __restrict__ bs1,
    const float* __restrict__ Wih1, const float* __restrict__ Whh1,
    const float* __restrict__ bih1, const float* __restrict__ bhh1,
    const float* __restrict__ Wp,   const float* __restrict__ bp,
    const float* __restrict__ Wih2, const float* __restrict__ Whh2,
    const float* __restrict__ bih2, const float* __restrict__ bhh2)
{
    const int tid  = threadIdx.x;
    const int warp = tid >> 5;
    const int lane = tid & 31;
    const int blk  = blockIdx.x;
    const bool isS = (blk < NB_S);
    const int rb   = blk - NB_S;

    float* s_whh  = sm + O_WHH;
    float* s_wih  = sm + O_WIH;
    float* s_bias = sm + O_BIAS;
    float* s_gates= sm + O_GATES;
    float* s_c    = sm + O_C;
    float* s_nh   = sm + O_NH;
    float* s_wp   = sm + O_WP;
    float* s_bp   = sm + O_BP;
    int*   s_ctrl = (int*)(sm + O_CTRL);
    float* s_gum  = sm + O_GUM;

    // ---------------- prologue ----------------
    if (tid < V) s_bp[tid] = bp[tid];
    for (int i = tid; i < TMAX * V; i += NT) s_gum[i] = gum[i];

    if (isS) {
        for (int i = tid; i < 4 * SLS * PADS; i += NT) {
            int r = i >> 8, k = i & (PADS - 1);
            int g = r / SLS, j = r - g * SLS;
            int R = g * H_S + blk * SLS + j;
            s_whh[i] = (k < H_S) ? Whh1[R * H_S + k] : 0.0f;
        }
        for (int i = tid; i < 4 * SLS * V; i += NT) {
            int r = i / V, k = i - r * V;
            int g = r / SLS, j = r - g * SLS;
            int R = g * H_S + blk * SLS + j;
            s_wih[i] = Wih1[R * V + k];
        }
        if (tid < 4 * SLS) {
            int g = tid / SLS, j = tid - g * SLS;
            int R = g * H_S + blk * SLS + j;
            s_bias[tid] = bih1[R] + bhh1[R];
        }
        if (tid < SLS) s_c[tid] = 0.0f;
        for (int i = tid; i < V * SLS; i += NT) {
            int r = i / SLS, j = i - r * SLS;
            s_wp[i] = Wp[r * H_S + blk * SLS + j];
        }
        // h0 rows
        for (int j = warp; j < SLS; j += 8) {
            int row = blk * SLS + j;
            const float4* wr = (const float4*)(Ws1 + (size_t)row * IN_N);
            const float4* xv = (const float4*)x;
            float acc = 0.0f;
            for (int i = lane; i < IN_N / 4; i += 32) {
                float4 w = wr[i], xx = xv[i];
                acc += w.x * xx.x + w.y * xx.y + w.z * xx.z + w.w * xx.w;
            }
#pragma unroll
            for (int o = 16; o; o >>= 1) acc += __shfl_xor_sync(0xffffffffu, acc, o);
            if (lane == 0) {
                float v = acc + bs1[row];
                g_nh[0][row] = v > 0.0f ? v : 0.0f;
            }
        }
    } else {
        for (int i = tid; i < 4 * SLR * PADR; i += NT) {
            int r = i >> 7, k = i & (PADR - 1);
            int g = r / SLR, j = r - g * SLR;
            int R = g * H_R + rb * SLR + j;
            s_whh[i] = (k < H_R) ? Whh2[R * H_R + k] : 0.0f;
        }
        for (int i = tid; i < 4 * SLR * V; i += NT) {
            int r = i / V, k = i - r * V;
            int g = r / SLR, j = r - g * SLR;
            int R = g * H_R + rb * SLR + j;
            s_wih[i] = Wih2[R * V + k];
        }
        if (tid < 4 * SLR) {
            int g = tid / SLR, j = tid - g * SLR;
            int R = g * H_R + rb * SLR + j;
            s_bias[tid] = bih2[R] + bhh2[R];
        }
        if (tid < SLR) s_c[tid] = 0.0f;
        // re-zero hr exchange buffers for this replay (single block)
        if (blk == NB_S && tid < PADR) { g_hr[0][tid] = 0.0f; g_hr[1][tid] = 0.0f; }
    }

    unsigned step = 1;
    grid_barrier(step, tid, blk); step++;

    // ---------------- segments ----------------
    // S(t): warp0 resolves sym(t-1) (t>=2) WHILE other warps run the big matvecs.
    // After join: column add + pointwise. One grid barrier per segment.
    for (int t = 1; t <= TMAX + 1; t++) {
        const int pp = (t - 1) & 1;     // parity of nh(t-1) / lp(t-1)

        if (warp == 0) {
            if (t >= 2) {
                if (t - 1 == TMAX) {
                    if (lane == 0) s_ctrl[0] = V - 1;    // forced EOS at max length
                } else {
                    // logits(t-1) = bp + gum[t-2] + sum_b lp(t-1)[v][b]
                    const float4* p4 = (const float4*)&g_lp[pp][lane][0];
                    float4 a0 = __ldcg(p4), a1 = __ldcg(p4 + 1), a2 = __ldcg(p4 + 2),
                           a3 = __ldcg(p4 + 3), a4 = __ldcg(p4 + 4), a5 = __ldcg(p4 + 5),
                           a6 = __ldcg(p4 + 6);
                    float l1 = s_bp[lane] + s_gum[(t - 2) * V + lane]
                             + ((a0.x + a0.y) + (a0.z + a0.w)) + ((a1.x + a1.y) + (a1.z + a1.w))
                             + ((a2.x + a2.y) + (a2.z + a2.w)) + ((a3.x + a3.y) + (a3.z + a3.w))
                             + ((a4.x + a4.y) + (a4.z + a4.w)) + ((a5.x + a5.y) + (a5.z + a5.w))
                             + ((a6.x + a6.y) + (a6.z + a6.w));
                    float bv = l1; int bi = lane;
                    if (lane < V - 32) {
                        int v2 = 32 + lane;
                        const float4* q4 = (const float4*)&g_lp[pp][v2][0];
                        float4 b0 = __ldcg(q4), b1 = __ldcg(q4 + 1), b2 = __ldcg(q4 + 2),
                               b3 = __ldcg(q4 + 3), b4 = __ldcg(q4 + 4), b5 = __ldcg(q4 + 5),
                               b6 = __ldcg(q4 + 6);
                        float l2 = s_bp[v2] + s_gum[(t - 2) * V + v2]
                                 + ((b0.x + b0.y) + (b0.z + b0.w)) + ((b1.x + b1.y) + (b1.z + b1.w))
                                 + ((b2.x + b2.y) + (b2.z + b2.w)) + ((b3.x + b3.y) + (b3.z + b3.w))
                                 + ((b4.x + b4.y) + (b4.z + b4.w)) + ((b5.x + b5.y) + (b5.z + b5.w))
                                 + ((b6.x + b6.y) + (b6.z + b6.w));
                        if (l2 > bv) { bv = l2; bi = v2; }   // strict: ties keep lower idx
                    }
#pragma unroll
                    for (int o = 16; o; o >>= 1) {
                        float ov = __shfl_xor_sync(0xffffffffu, bv, o);
                        int   oi = __shfl_xor_sync(0xffffffffu, bi, o);
                        if (ov > bv || (ov == bv && oi < bi)) { bv = ov; bi = oi; }
                    }
                    if (lane == 0) s_ctrl[0] = bi;
                }
            }
        } else if (isS && warp <= 5) {
            // sender matvec: 40 gate rows, 8 per warp (warps 1..5)
            float4 h0v = __ldcg((const float4*)g_nh[pp] + lane);
            float4 h1v = __ldcg((const float4*)g_nh[pp] + 32 + lane);
            float acc[8];
#pragma unroll
            for (int u = 0; u < 8; u++) {
                const float4* wr = (const float4*)(s_whh + ((warp - 1) * 8 + u) * PADS);
                float4 w0 = wr[lane], w1 = wr[lane + 32];
                acc[u] = w0.x * h0v.x + w0.y * h0v.y + w0.z * h0v.z + w0.w * h0v.w
                       + w1.x * h1v.x + w1.y * h1v.y + w1.z * h1v.z + w1.w * h1v.w;
            }
#pragma unroll
            for (int o = 16; o; o >>= 1) {
#pragma unroll
                for (int u = 0; u < 8; u++) acc[u] += __shfl_xor_sync(0xffffffffu, acc[u], o);
            }
            if (lane == 0) {
#pragma unroll
                for (int u = 0; u < 8; u++) {
                    int r = (warp - 1) * 8 + u;
                    s_gates[r] = acc[u] + s_bias[r];
                }
            }
        } else if (!isS && t >= 2) {
            // receiver matvec: 80 gate rows, 12 per warp (warps 1..7)
            float4 hv = __ldcg((const float4*)g_hr[t & 1] + lane);   // hr(t-2)
            float acc[12];
#pragma unroll
            for (int u = 0; u < 12; u++) {
                int r = (warp - 1) * 12 + u;
                if (r < 4 * SLR) {
                    float4 w = ((const float4*)(s_whh + r * PADR))[lane];
                    acc[u] = w.x * hv.x + w.y * hv.y + w.z * hv.z + w.w * hv.w;
                } else acc[u] = 0.0f;
            }
#pragma unroll
            for (int o = 16; o; o >>= 1) {
#pragma unroll
                for (int u = 0; u < 12; u++) acc[u] += __shfl_xor_sync(0xffffffffu, acc[u], o);
            }
            if (lane == 0) {
#pragma unroll
                for (int u = 0; u < 12; u++) {
                    int r = (warp - 1) * 12 + u;
                    if (r < 4 * SLR) s_gates[r] = acc[u] + s_bias[r];
                }
            }
        }
        __syncthreads();   // join: gates ready AND sym resolved

        const int sym = (t >= 2) ? s_ctrl[0] : -1;
        const bool last = (sym == V - 1);

        if (!isS && t >= 2 && tid < SLR) {       // receiver pointwise: hr(t-1)
            float gi = s_gates[tid]           + s_wih[(tid)           * V + sym];
            float gf = s_gates[SLR + tid]     + s_wih[(SLR + tid)     * V + sym];
            float gg = s_gates[2 * SLR + tid] + s_wih[(2 * SLR + tid) * V + sym];
            float go = s_gates[3 * SLR + tid] + s_wih[(3 * SLR + tid) * V + sym];
            float cn = fsig(gf) * s_c[tid] + fsig(gi) * ftanh(gg);
            s_c[tid] = cn;
            float hr = fsig(go) * ftanh(cn);
            if (last) g_hr_final[rb * SLR + tid] = hr;
            else      g_hr[(t - 1) & 1][rb * SLR + tid] = hr;
        }
        if (last) break;

        if (isS && tid < SLS) {                  // sender pointwise: nh(t)
            float gi = s_gates[tid],           gf = s_gates[SLS + tid];
            float gg = s_gates[2 * SLS + tid], go = s_gates[3 * SLS + tid];
            if (sym >= 0) {
                gi += s_wih[(tid)           * V + sym];
                gf += s_wih[(SLS + tid)     * V + sym];
                gg += s_wih[(2 * SLS + tid) * V + sym];
                go += s_wih[(3 * SLS + tid) * V + sym];
            }
            float cn = fsig(gf) * s_c[tid] + fsig(gi) * ftanh(gg);
            s_c[tid] = cn;
            float nh = fsig(go) * ftanh(cn);
            s_nh[tid] = nh;
            g_nh[t & 1][blk * SLS + tid] = nh;
        }
        __syncthreads();
        if (isS && tid < V) {                    // partial logits lp(t)
            float a = 0.0f;
#pragma unroll
            for (int j = 0; j < SLS; j++) a += s_wp[tid * SLS + j] * s_nh[j];
            g_lp[t & 1][tid][blk] = a;
        }

        grid_barrier(step, tid, blk); step++;
    }
}

// ---------------- final stage: softmax(W_r @ hR + b_r) ----------------
// Register-rotation version with SOFTWARE PIPELINING: prefetch group b+1's four
// rows before reducing group b (MLP 4 -> 8, shfl chain overlapped with loads).
// logits tiny (weights *0.05, |h|<1): exp can't overflow, no max subtraction.

__global__ void __launch_bounds__(256) k_logits(const float* __restrict__ Wr,
                                                const float* __restrict__ br,
                                                float* __restrict__ out)
{
    __shared__ float sh[PADR];
    __shared__ float wsum[8];
    __shared__ float red[256];
    __shared__ int isLast;
    int tid = threadIdx.x, warp = tid >> 5, lane = tid & 31;
    if (tid < H_R) sh[tid] = g_hr_final[tid];
    else if (tid < PADR) sh[tid] = 0.0f;
    __syncthreads();

    const bool ld = (lane < H_R / 4);
    float4 hv = make_float4(0.f, 0.f, 0.f, 0.f);
    if (ld) hv = ((const float4*)sh)[lane];

    int base = (blockIdx.x * 8 + warp) * 32;
    float myacc = 0.0f;
    float4 w[4], wn[4];
    const float4 zero = make_float4(0.f, 0.f, 0.f, 0.f);
#pragma unroll
    for (int j = 0; j < 4; j++)
        w[j] = ld ? __ldg((const float4*)(Wr + (size_t)(base + j) * H_R) + lane) : zero;
#pragma unroll
    for (int b = 0; b < 8; b++) {
        if (b < 7) {
#pragma unroll
            for (int j = 0; j < 4; j++)
                wn[j] = ld ? __ldg((const float4*)(Wr + (size_t)(base + (b + 1) * 4 + j) * H_R) + lane) : zero;
        }
        float acc[4];
#pragma unroll
        for (int j = 0; j < 4; j++)
            acc[j] = w[j].x * hv.x + w[j].y * hv.y + w[j].z * hv.z + w[j].w * hv.w;
#pragma unroll
        for (int o = 16; o; o >>= 1) {
#pragma unroll
            for (int j = 0; j < 4; j++) acc[j] += __shfl_xor_sync(0xffffffffu, acc[j], o);
        }
#pragma unroll
        for (int j = 0; j < 4; j++)
            if (lane == b * 4 + j) myacc = acc[j];   // rotate: lane i keeps row base+i
#pragma unroll
        for (int j = 0; j < 4; j++) w[j] = wn[j];
    }
    float e = __expf(myacc + br[base + lane]);
    out[base + lane] = e;                            // fully coalesced store
    float es = e;
#pragma unroll
    for (int o = 16; o; o >>= 1) es += __shfl_xor_sync(0xffffffffu, es, o);
    if (lane == 0) wsum[warp] = es;
    __syncthreads();
    if (tid == 0) {
        float s2 = 0.0f;
#pragma unroll
        for (int w2 = 0; w2 < 8; w2++) s2 += wsum[w2];
        g_partials[blockIdx.x] = s2;                 // fixed order: deterministic
        unsigned old;
        asm volatile("atom.acq_rel.gpu.global.add.u32 %0, [%1], 1;"
                     : "=r"(old) : "l"(&g_done) : "memory");
        isLast = (old == 1023u);
    }
    __syncthreads();
    if (isLast) {
        float s = g_partials[tid] + g_partials[tid + 256]
                + g_partials[tid + 512] + g_partials[tid + 768];  // fixed order
        red[tid] = s;
        __syncthreads();
#pragma unroll
        for (int o = 128; o; o >>= 1) {
            if (tid < o) red[tid] += red[tid + o];
            __syncthreads();
        }
        if (tid == 0) {
            g_inv = 1.0f / red[0];
            g_done = 0u;                             // self-reset for next replay
        }
    }
}

__global__ void __launch_bounds__(256) k_scale(float* __restrict__ out)
{
    int i = blockIdx.x * 256 + threadIdx.x;
    out[i] *= g_inv;
    if (blockIdx.x == 0 && threadIdx.x < NB) g_flags[threadIdx.x].v = 0u;  // reset barrier
}

extern "C" void kernel_launch(void* const* d_in, const int* in_sizes, int n_in,
                              void* d_out, int out_size)
{
    (void)in_sizes; (void)n_in; (void)out_size;
    const float* x    = (const float*)d_in[0];
    const float* gum  = (const float*)d_in[1];
    const float* Ws1  = (const float*)d_in[2];
    const float* bs1  = (const float*)d_in[3];
    const float* Wih1 = (const float*)d_in[4];
    const float* Whh1 = (const float*)d_in[5];
    const float* bih1 = (const float*)d_in[6];
    const float* bhh1 = (const float*)d_in[7];
    const float* Wp   = (const float*)d_in[8];
    const float* bp   = (const float*)d_in[9];
    const float* Wih2 = (const float*)d_in[10];
    const float* Whh2 = (const float*)d_in[11];
    const float* bih2 = (const float*)d_in[12];
    const float* bhh2 = (const float*)d_in[13];
    const float* Wr   = (const float*)d_in[14];
    const float* br   = (const float*)d_in[15];
    float* out = (float*)d_out;

    cudaFuncSetAttribute(net_kernel, cudaFuncAttributeMaxDynamicSharedMemorySize, SMEM_BYTES);

    net_kernel<<<NB, NT, SMEM_BYTES>>>(x, gum, Ws1, bs1, Wih1, Whh1, bih1, bhh1,
                                       Wp, bp, Wih2, Whh2, bih2, bhh2);
    k_logits<<<1024, 256>>>(Wr, br, out);
    k_scale<<<OUT_N / 256, 256>>>(out);
}

// round 17
// speedup vs baseline: 1.2382x; 1.0114x over previous
#include <cuda_runtime.h>
#include <math.h>

#define IN_N   4096
#define H_S    250
#define H_R    100
#define V      40
#define TMAX   30
#define OUT_N  262144
#define NB_S   25
#define NB_R   5
#define NB     30
#define SLS    10       // sender h rows per block
#define SLR    20       // receiver h rows per block
#define NT     256
#define PADS   256
#define PADR   128
#define NREP   5        // nh replication factor (spreads L2 slice hotspot)

// ---- global scratch (no allocations; zero-initialized at load) ----
__device__ __align__(16) float g_nh[2][NREP][PADS]; // sender hidden, parity+replica (pads stay 0)
__device__ __align__(16) float g_hr[2][PADR];   // receiver hidden, parity buffered
__device__ __align__(16) float g_lp[2][V][32];  // partial logits; slots 25..31 stay 0 forever
__device__ __align__(16) float g_hr_final[H_R];
struct Flag128 { unsigned v; unsigned pad[31]; };
__device__ Flag128  g_flags[NB];                // reset by k_logits last block
__device__ unsigned g_done;                     // k_logits arrival counter (reset by net_kernel)
__device__ unsigned g_flag2;                    // k_logits inv-ready flag  (reset by net_kernel)
__device__ float    g_partials[512];
__device__ float    g_inv;

// ---- smem layout (floats) ----
#define O_WHH   0       // 10240  (S: 40x256, R: 80x128 — both 10240)
#define O_WIH   10240   // 3200   (S: 40x40, R: 80x40)
#define O_BIAS  13440   // 80
#define O_GATES 13520   // 80
#define O_C     13600   // 20
#define O_WP    13620   // 400
#define O_BP    14020   // 40
#define O_CTRL  14060   // 4
#define O_GUM   14064   // 1200
#define SMEM_FLOATS 15264
#define SMEM_BYTES  (SMEM_FLOATS * 4)

__device__ __forceinline__ float fsig(float v)  { return __fdividef(1.0f, 1.0f + __expf(-v)); }
__device__ __forceinline__ float ftanh(float v) { return 1.0f - __fdividef(2.0f, __expf(2.0f * v) + 1.0f); }

// Contention-free grid barrier: arrivals and polls hit DISTINCT L2 lines.
__device__ __forceinline__ void grid_barrier(unsigned step, int tid, int blk) {
    __syncthreads();
    if (tid == 0)
        asm volatile("st.release.gpu.global.u32 [%0], %1;"
                     :: "l"(&g_flags[blk].v), "r"(step) : "memory");
    if (tid < NB) {
        unsigned v;
        do {
            asm volatile("ld.acquire.gpu.u32 %0, [%1];"
                         : "=r"(v) : "l"(&g_flags[tid].v) : "memory");
        } while (v < step);
    }
    __syncthreads();
}

extern __shared__ float sm[];

__global__ void __launch_bounds__(NT) net_kernel(
    const float* __restrict__ x,    const float* __restrict__ gum,
    const float* __restrict__ Ws1,  const float* __restrict__ bs1,
    const float* __restrict__ Wih1, const float* __restrict__ Whh1,
    const float* __restrict__ bih1, const float* __restrict__ bhh1,
    const float* __restrict__ Wp,   const float* __restrict__ bp,
    const float* __restrict__ Wih2, const float* __restrict__ Whh2,
    const float* __restrict__ bih2, const float* __restrict__ bhh2)
{
    const int tid  = threadIdx.x;
    const int warp = tid >> 5;
    const int lane = tid & 31;
    const int blk  = blockIdx.x;
    const bool isS = (blk < NB_S);
    const int rb   = blk - NB_S;
    const int rep  = blk % NREP;

    float* s_whh  = sm + O_WHH;
    float* s_wih  = sm + O_WIH;
    float* s_bias = sm + O_BIAS;
    float* s_gates= sm + O_GATES;
    float* s_c    = sm + O_C;
    float* s_wp   = sm + O_WP;
    float* s_bp   = sm + O_BP;
    int*   s_ctrl = (int*)(sm + O_CTRL);
    float* s_gum  = sm + O_GUM;

    // reset k_logits finalizer state for THIS replay (stream order: before k_logits)
    if (blk == 0 && tid == 0) { g_done = 0u; g_flag2 = 0u; }

    // ---------------- prologue ----------------
    if (tid < V) s_bp[tid] = bp[tid];
    for (int i = tid; i < TMAX * V; i += NT) s_gum[i] = gum[i];

    if (isS) {
        for (int i = tid; i < 4 * SLS * PADS; i += NT) {
            int r = i >> 8, k = i & (PADS - 1);
            int g = r / SLS, j = r - g * SLS;
            int R = g * H_S + blk * SLS + j;
            s_whh[i] = (k < H_S) ? Whh1[R * H_S + k] : 0.0f;
        }
        for (int i = tid; i < 4 * SLS * V; i += NT) {
            int r = i / V, k = i - r * V;
            int g = r / SLS, j = r - g * SLS;
            int R = g * H_S + blk * SLS + j;
            s_wih[i] = Wih1[R * V + k];
        }
        if (tid < 4 * SLS) {
            int g = tid / SLS, j = tid - g * SLS;
            int R = g * H_S + blk * SLS + j;
            s_bias[tid] = bih1[R] + bhh1[R];
        }
        if (tid < SLS) s_c[tid] = 0.0f;
        for (int i = tid; i < V * SLS; i += NT) {
            int r = i / SLS, j = i - r * SLS;
            s_wp[i] = Wp[r * H_S + blk * SLS + j];
        }
        // h0 rows (write all replicas)
        for (int j = warp; j < SLS; j += 8) {
            int row = blk * SLS + j;
            const float4* wr = (const float4*)(Ws1 + (size_t)row * IN_N);
            const float4* xv = (const float4*)x;
            float acc = 0.0f;
            for (int i = lane; i < IN_N / 4; i += 32) {
                float4 w = wr[i], xx = xv[i];
                acc += w.x * xx.x + w.y * xx.y + w.z * xx.z + w.w * xx.w;
            }
#pragma unroll
            for (int o = 16; o; o >>= 1) acc += __shfl_xor_sync(0xffffffffu, acc, o);
            if (lane == 0) {
                float v = acc + bs1[row];
                float h0 = v > 0.0f ? v : 0.0f;
#pragma unroll
                for (int r2 = 0; r2 < NREP; r2++) g_nh[0][r2][row] = h0;
            }
        }
    } else {
        for (int i = tid; i < 4 * SLR * PADR; i += NT) {
            int r = i >> 7, k = i & (PADR - 1);
            int g = r / SLR, j = r - g * SLR;
            int R = g * H_R + rb * SLR + j;
            s_whh[i] = (k < H_R) ? Whh2[R * H_R + k] : 0.0f;
        }
        for (int i = tid; i < 4 * SLR * V; i += NT) {
            int r = i / V, k = i - r * V;
            int g = r / SLR, j = r - g * SLR;
            int R = g * H_R + rb * SLR + j;
            s_wih[i] = Wih2[R * V + k];
        }
        if (tid < 4 * SLR) {
            int g = tid / SLR, j = tid - g * SLR;
            int R = g * H_R + rb * SLR + j;
            s_bias[tid] = bih2[R] + bhh2[R];
        }
        if (tid < SLR) s_c[tid] = 0.0f;
        // re-zero hr exchange buffers for this replay (single block)
        if (blk == NB_S && tid < PADR) { g_hr[0][tid] = 0.0f; g_hr[1][tid] = 0.0f; }
    }

    unsigned step = 1;
    grid_barrier(step, tid, blk); step++;

    // ---------------- segments ----------------
    // S(t): warp0 resolves sym(t-1) (t>=2) WHILE other warps run the big matvecs.
    // After join: warp0 does column add + pointwise + fused lp (shfl broadcast).
    for (int t = 1; t <= TMAX + 1; t++) {
        const int pp = (t - 1) & 1;     // parity of nh(t-1) / lp(t-1)

        if (warp == 0) {
            if (t >= 2) {
                if (t - 1 == TMAX) {
                    if (lane == 0) s_ctrl[0] = V - 1;    // forced EOS at max length
                } else {
                    // logits(t-1) = bp + gum[t-2] + sum_b lp(t-1)[v][b]
                    const float4* p4 = (const float4*)&g_lp[pp][lane][0];
                    float4 a0 = __ldcg(p4), a1 = __ldcg(p4 + 1), a2 = __ldcg(p4 + 2),
                           a3 = __ldcg(p4 + 3), a4 = __ldcg(p4 + 4), a5 = __ldcg(p4 + 5),
                           a6 = __ldcg(p4 + 6);
                    float bv = s_bp[lane] + s_gum[(t - 2) * V + lane]
                             + ((a0.x + a0.y) + (a0.z + a0.w)) + ((a1.x + a1.y) + (a1.z + a1.w))
                             + ((a2.x + a2.y) + (a2.z + a2.w)) + ((a3.x + a3.y) + (a3.z + a3.w))
                             + ((a4.x + a4.y) + (a4.z + a4.w)) + ((a5.x + a5.y) + (a5.z + a5.w))
                             + ((a6.x + a6.y) + (a6.z + a6.w));
                    int bi = lane;
                    if (lane < V - 32) {
                        int v2 = 32 + lane;
                        const float4* q4 = (const float4*)&g_lp[pp][v2][0];
                        float4 b0 = __ldcg(q4), b1 = __ldcg(q4 + 1), b2 = __ldcg(q4 + 2),
                               b3 = __ldcg(q4 + 3), b4 = __ldcg(q4 + 4), b5 = __ldcg(q4 + 5),
                               b6 = __ldcg(q4 + 6);
                        float l2 = s_bp[v2] + s_gum[(t - 2) * V + v2]
                                 + ((b0.x + b0.y) + (b0.z + b0.w)) + ((b1.x + b1.y) + (b1.z + b1.w))
                                 + ((b2.x + b2.y) + (b2.z + b2.w)) + ((b3.x + b3.y) + (b3.z + b3.w))
                                 + ((b4.x + b4.y) + (b4.z + b4.w)) + ((b5.x + b5.y) + (b5.z + b5.w))
                                 + ((b6.x + b6.y) + (b6.z + b6.w));
                        if (l2 > bv) { bv = l2; bi = v2; }   // strict: ties keep lower idx
                    }
#pragma unroll
                    for (int o = 16; o; o >>= 1) {
                        float ov = __shfl_xor_sync(0xffffffffu, bv, o);
                        int   oi = __shfl_xor_sync(0xffffffffu, bi, o);
                        if (ov > bv || (ov == bv && oi < bi)) { bv = ov; bi = oi; }
                    }
                    if (lane == 0) s_ctrl[0] = bi;
                }
            }
        } else if (isS && warp <= 5) {
            // sender matvec: 40 gate rows, 8 per warp (warps 1..5); read own replica
            const float4* nh4 = (const float4*)g_nh[pp][rep];
            float4 h0v = __ldcg(nh4 + lane);
            float4 h1v = __ldcg(nh4 + 32 + lane);
            float acc[8];
#pragma unroll
            for (int u = 0; u < 8; u++) {
                const float4* wr = (const float4*)(s_whh + ((warp - 1) * 8 + u) * PADS);
                float4 w0 = wr[lane], w1 = wr[lane + 32];
                acc[u] = w0.x * h0v.x + w0.y * h0v.y + w0.z * h0v.z + w0.w * h0v.w
                       + w1.x * h1v.x + w1.y * h1v.y + w1.z * h1v.z + w1.w * h1v.w;
            }
#pragma unroll
            for (int o = 16; o; o >>= 1) {
#pragma unroll
                for (int u = 0; u < 8; u++) acc[u] += __shfl_xor_sync(0xffffffffu, acc[u], o);
            }
            if (lane == 0) {
#pragma unroll
                for (int u = 0; u < 8; u++) {
                    int r = (warp - 1) * 8 + u;
                    s_gates[r] = acc[u] + s_bias[r];
                }
            }
        } else if (!isS && t >= 2) {
            // receiver matvec: 80 gate rows, 12 per warp (warps 1..7)
            float4 hv = __ldcg((const float4*)g_hr[t & 1] + lane);   // hr(t-2)
            float acc[12];
#pragma unroll
            for (int u = 0; u < 12; u++) {
                int r = (warp - 1) * 12 + u;
                if (r < 4 * SLR) {
                    float4 w = ((const float4*)(s_whh + r * PADR))[lane];
                    acc[u] = w.x * hv.x + w.y * hv.y + w.z * hv.z + w.w * hv.w;
                } else acc[u] = 0.0f;
            }
#pragma unroll
            for (int o = 16; o; o >>= 1) {
#pragma unroll
                for (int u = 0; u < 12; u++) acc[u] += __shfl_xor_sync(0xffffffffu, acc[u], o);
            }
            if (lane == 0) {
#pragma unroll
                for (int u = 0; u < 12; u++) {
                    int r = (warp - 1) * 12 + u;
                    if (r < 4 * SLR) s_gates[r] = acc[u] + s_bias[r];
                }
            }
        }
        __syncthreads();   // join: gates ready AND sym resolved

        const int sym = (t >= 2) ? s_ctrl[0] : -1;
        const bool last = (sym == V - 1);

        if (!isS && t >= 2 && tid < SLR) {       // receiver pointwise: hr(t-1)
            float gi = s_gates[tid]           + s_wih[(tid)           * V + sym];
            float gf = s_gates[SLR + tid]     + s_wih[(SLR + tid)     * V + sym];
            float gg = s_gates[2 * SLR + tid] + s_wih[(2 * SLR + tid) * V + sym];
            float go = s_gates[3 * SLR + tid] + s_wih[(3 * SLR + tid) * V + sym];
            float cn = fsig(gf) * s_c[tid] + fsig(gi) * ftanh(gg);
            s_c[tid] = cn;
            float hr = fsig(go) * ftanh(cn);
            if (last) g_hr_final[rb * SLR + tid] = hr;
            else      g_hr[(t - 1) & 1][rb * SLR + tid] = hr;
        }
        if (last) break;

        if (isS && warp == 0) {
            // sender pointwise (lanes 0..9) + fused lp via shfl broadcast (all lanes)
            float nhv = 0.0f;
            if (lane < SLS) {
                float gi = s_gates[lane],           gf = s_gates[SLS + lane];
                float gg = s_gates[2 * SLS + lane], go = s_gates[3 * SLS + lane];
                if (sym >= 0) {
                    gi += s_wih[(lane)           * V + sym];
                    gf += s_wih[(SLS + lane)     * V + sym];
                    gg += s_wih[(2 * SLS + lane) * V + sym];
                    go += s_wih[(3 * SLS + lane) * V + sym];
                }
                float cn = fsig(gf) * s_c[lane] + fsig(gi) * ftanh(gg);
                s_c[lane] = cn;
                nhv = fsig(go) * ftanh(cn);
#pragma unroll
                for (int r2 = 0; r2 < NREP; r2++)
                    g_nh[t & 1][r2][blk * SLS + lane] = nhv;
            }
            float h[SLS];
#pragma unroll
            for (int j = 0; j < SLS; j++) h[j] = __shfl_sync(0xffffffffu, nhv, j);
            {
                const float* wv = s_wp + lane * SLS;
                float a = 0.0f;
#pragma unroll
                for (int j = 0; j < SLS; j++) a += wv[j] * h[j];
                g_lp[t & 1][lane][blk] = a;
            }
            if (lane < V - 32) {
                int v2 = 32 + lane;
                const float* wv = s_wp + v2 * SLS;
                float a = 0.0f;
#pragma unroll
                for (int j = 0; j < SLS; j++) a += wv[j] * h[j];
                g_lp[t & 1][v2][blk] = a;
            }
        }

        grid_barrier(step, tid, blk); step++;
    }
}

// ---------------- final stage: softmax(W_r @ hR + b_r), fused normalize ----------------
// Persistent 512-block grid (launch_bounds(256,4): 592 resident slots >= 512, no deadlock).
// Pipelined loads (prefetch next 4-row group), rotation into e0/e1; last-arriving block
// reduces 512 partials and release-stores the inv flag; all blocks spin then scale
// register-resident exp values. logits tiny: exp can't overflow, no max subtraction.

__global__ void __launch_bounds__(256, 4) k_logits(const float* __restrict__ Wr,
                                                   const float* __restrict__ br,
                                                   float* __restrict__ out)
{
    __shared__ float sh[PADR];
    __shared__ float wsum[8];
    __shared__ float red[256];
    __shared__ int isLast;
    int tid = threadIdx.x, warp = tid >> 5, lane = tid & 31;
    if (tid < H_R) sh[tid] = g_hr_final[tid];
    else if (tid < PADR) sh[tid] = 0.0f;
    __syncthreads();

    const bool ld = (lane < H_R / 4);
    float4 hv = make_float4(0.f, 0.f, 0.f, 0.f);
    if (ld) hv = ((const float4*)sh)[lane];

    int base = blockIdx.x * 512 + warp * 64;
    float e0acc = 0.0f, e1acc = 0.0f;
    float4 w[4], wn[4];
    const float4 zero = make_float4(0.f, 0.f, 0.f, 0.f);
#pragma unroll
    for (int j = 0; j < 4; j++)
        w[j] = ld ? __ldg((const float4*)(Wr + (size_t)(base + j) * H_R) + lane) : zero;
#pragma unroll
    for (int b = 0; b < 16; b++) {
        if (b < 15) {
#pragma unroll
            for (int j = 0; j < 4; j++)
                wn[j] = ld ? __ldg((const float4*)(Wr + (size_t)(base + (b + 1) * 4 + j) * H_R) + lane) : zero;
        }
        float acc[4];
#pragma unroll
        for (int j = 0; j < 4; j++)
            acc[j] = w[j].x * hv.x + w[j].y * hv.y + w[j].z * hv.z + w[j].w * hv.w;
#pragma unroll
        for (int o = 16; o; o >>= 1) {
#pragma unroll
            for (int j = 0; j < 4; j++) acc[j] += __shfl_xor_sync(0xffffffffu, acc[j], o);
        }
        if (b < 8) {
#pragma unroll
            for (int j = 0; j < 4; j++)
                if (lane == b * 4 + j) e0acc = acc[j];    // rows base .. base+31
        } else {
#pragma unroll
            for (int j = 0; j < 4; j++)
                if (lane == (b - 8) * 4 + j) e1acc = acc[j];  // rows base+32 .. base+63
        }
#pragma unroll
        for (int j = 0; j < 4; j++) w[j] = wn[j];
    }
    float e0 = __expf(e0acc + br[base + lane]);
    float e1 = __expf(e1acc + br[base + 32 + lane]);
    float es = e0 + e1;
#pragma unroll
    for (int o = 16; o; o >>= 1) es += __shfl_xor_sync(0xffffffffu, es, o);
    if (lane == 0) wsum[warp] = es;
    __syncthreads();
    if (tid == 0) {
        float s2 = 0.0f;
#pragma unroll
        for (int w2 = 0; w2 < 8; w2++) s2 += wsum[w2];
        g_partials[blockIdx.x] = s2;                 // fixed order: deterministic
        unsigned old;
        asm volatile("atom.acq_rel.gpu.global.add.u32 %0, [%1], 1;"
                     : "=r"(old) : "l"(&g_done) : "memory");
        isLast = (old == 511u);
    }
    __syncthreads();
    if (isLast) {
        float s = g_partials[tid] + g_partials[tid + 256];   // fixed order: deterministic
        red[tid] = s;
        __syncthreads();
#pragma unroll
        for (int o = 128; o; o >>= 1) {
            if (tid < o) red[tid] += red[tid + o];
            __syncthreads();
        }
        if (tid == 0) {
            __stcg(&g_inv, 1.0f / red[0]);
            asm volatile("st.release.gpu.global.u32 [%0], 1;" :: "l"(&g_flag2) : "memory");
        }
        if (tid < NB) g_flags[tid].v = 0u;       // reset net barrier flags for next replay
    }
    if (tid == 0) {
        unsigned f;
        do {
            asm volatile("ld.acquire.gpu.u32 %0, [%1];" : "=r"(f) : "l"(&g_flag2) : "memory");
        } while (f == 0u);
    }
    __syncthreads();
    float inv = __ldcg(&g_inv);
    out[base + lane]      = e0 * inv;            // fully coalesced stores
    out[base + 32 + lane] = e1 * inv;
}

extern "C" void kernel_launch(void* const* d_in, const int* in_sizes, int n_in,
                              void* d_out, int out_size)
{
    (void)in_sizes; (void)n_in; (void)out_size;
    const float* x    = (const float*)d_in[0];
    const float* gum  = (const float*)d_in[1];
    const float* Ws1  = (const float*)d_in[2];
    const float* bs1  = (const float*)d_in[3];
    const float* Wih1 = (const float*)d_in[4];
    const float* Whh1 = (const float*)d_in[5];
    const float* bih1 = (const float*)d_in[6];
    const float* bhh1 = (const float*)d_in[7];
    const float* Wp   = (const float*)d_in[8];
    const float* bp   = (const float*)d_in[9];
    const float* Wih2 = (const float*)d_in[10];
    const float* Whh2 = (const float*)d_in[11];
    const float* bih2 = (const float*)d_in[12];
    const float* bhh2 = (const float*)d_in[13];
    const float* Wr   = (const float*)d_in[14];
    const float* br   = (const float*)d_in[15];
    float* out = (float*)d_out;

    cudaFuncSetAttribute(net_kernel, cudaFuncAttributeMaxDynamicSharedMemorySize, SMEM_BYTES);

    net_kernel<<<NB, NT, SMEM_BYTES>>>(x, gum, Ws1, bs1, Wih1, Whh1, bih1, bhh1,
                                       Wp, bp, Wih2, Whh2, bih2, bhh2);
    k_logits<<<512, 256>>>(Wr, br, out);
}